// round 8
// baseline (speedup 1.0000x reference)
#include <cuda_runtime.h>

#define B_      32
#define DIM_    4096
#define NH_     32
#define NKV_    8
#define HD_     128
#define NREP_   4
#define T_TOT   2048
#define START_  2047
#define QKV_N   6144
#define SK_     8
#define TILE_N  128
#define TILE_K  32
#define SPLITS_ 4
#define TOK_PER_SPLIT 512
#define TOK_PER_WARP  128
#define NPART_  16   // SPLITS_ * 4 warps

typedef unsigned long long ull;

// ---------------- scratch (device globals; no runtime allocation) ----------
__device__ float g_part[SK_ * B_ * QKV_N];          // GEMM split-K partials
__device__ float g_qkv [B_ * QKV_N];                // fused q|k|v after reduce+rope
__device__ float g_attn[B_ * NH_ * HD_];            // attention output
__device__ float g_pm  [B_ * NH_ * NPART_];
__device__ float g_pl  [B_ * NH_ * NPART_];
__device__ float g_po  [(size_t)B_ * NH_ * NPART_ * HD_];

// packed fp32x2 FMA: d += a * b (elementwise pairs). PTX-only path; 2x fp32 rate.
__device__ __forceinline__ void ffma2(ull& d, ull a, ull b)
{
    asm("fma.rn.f32x2 %0, %1, %2, %0;" : "+l"(d) : "l"(a), "l"(b));
}
// broadcast one float into both halves of a 64-bit pair
__device__ __forceinline__ ull bcast2(float f)
{
    ull d;
    unsigned r = __float_as_uint(f);
    asm("mov.b64 %0, {%1, %1};" : "=l"(d) : "r"(r));
    return d;
}

// ---------------- split-K tall-skinny GEMM with K-pair FFMA2 ---------------
__device__ __forceinline__ void gemm_body(const float* __restrict__ A,
                                          const float* __restrict__ W,
                                          int N, int col0, int n0, int ky)
{
    __shared__ float xs[B_][TILE_K + 2];
    __shared__ float ws[TILE_N][TILE_K + 2];

    const int kbeg = ky * (DIM_ / SK_);
    const int tid  = threadIdx.x;
    const int tx   = tid & 15;
    const int ty   = tid >> 4;

    ull acc[4][8];
#pragma unroll
    for (int i = 0; i < 4; i++)
#pragma unroll
        for (int j = 0; j < 8; j++) acc[i][j] = 0ull;

    for (int kt = 0; kt < DIM_ / SK_; kt += TILE_K) {
        const int k0 = kbeg + kt;
#pragma unroll
        for (int it = 0; it < (TILE_K * TILE_N) / 128; it++) {
            int idx = tid + it * 128;
            int kk = idx >> 7;
            int nn = idx & 127;
            ws[nn][kk] = W[(size_t)(k0 + kk) * N + n0 + nn];
        }
#pragma unroll
        for (int it = 0; it < (B_ * TILE_K) / 128; it++) {
            int idx = tid + it * 128;
            int bb = idx >> 5;
            int kk = idx & 31;
            xs[bb][kk] = A[(size_t)bb * DIM_ + k0 + kk];
        }
        __syncthreads();
#pragma unroll
        for (int kp = 0; kp < TILE_K / 2; kp++) {
            ull xv[4], wv[8];
#pragma unroll
            for (int i = 0; i < 4; i++)
                xv[i] = *reinterpret_cast<const ull*>(&xs[ty + 8 * i][2 * kp]);
#pragma unroll
            for (int j = 0; j < 8; j++)
                wv[j] = *reinterpret_cast<const ull*>(&ws[tx + 16 * j][2 * kp]);
#pragma unroll
            for (int i = 0; i < 4; i++)
#pragma unroll
                for (int j = 0; j < 8; j++)
                    ffma2(acc[i][j], xv[i], wv[j]);
        }
        __syncthreads();
    }
#pragma unroll
    for (int i = 0; i < 4; i++) {
        int bb = ty + 8 * i;
#pragma unroll
        for (int j = 0; j < 8; j++) {
            float2 v = *reinterpret_cast<const float2*>(&acc[i][j]);
            int nn = col0 + n0 + tx + 16 * j;
            g_part[((size_t)ky * B_ + bb) * QKV_N + nn] = v.x + v.y;
        }
    }
}

__global__ void __launch_bounds__(128)
gemm_qkv(const float* __restrict__ x, const float* __restrict__ wq,
         const float* __restrict__ wk, const float* __restrict__ wv)
{
    const int tile = blockIdx.x;
    const int ky   = blockIdx.y;
    if (tile < 32)       gemm_body(x, wq, 4096, 0,    tile * TILE_N,        ky);
    else if (tile < 40)  gemm_body(x, wk, 1024, 4096, (tile - 32) * TILE_N, ky);
    else                 gemm_body(x, wv, 1024, 5120, (tile - 40) * TILE_N, ky);
}

__global__ void __launch_bounds__(128)
gemm_o(const float* __restrict__ W)
{
    gemm_body(g_attn, W, 4096, 0, blockIdx.x * TILE_N, blockIdx.y);
}

// ---------------- fused reduce + RoPE (float2 pairs) -----------------------
__global__ void reduce_rope(const float* __restrict__ fc, const float* __restrict__ fs)
{
    const int idx = blockIdx.x * blockDim.x + threadIdx.x;  // pair index, 32*3072
    const int b2  = idx / 3072;
    const int cp  = idx - b2 * 3072;
    float2 s = make_float2(0.f, 0.f);
#pragma unroll
    for (int ky = 0; ky < SK_; ky++) {
        float2 v = reinterpret_cast<const float2*>(g_part)[(size_t)(ky * B_ + b2) * 3072 + cp];
        s.x += v.x; s.y += v.y;
    }
    if (cp < 2560) {  // q (cp<2048) and k (2048..2559) get RoPE
        int f = cp & 63;
        float c = fc[f], sn = fs[f];
        float xr = s.x, xi = s.y;
        s.x = xr * c - xi * sn;
        s.y = xr * sn + xi * c;
    }
    reinterpret_cast<float2*>(g_qkv)[(size_t)b2 * 3072 + cp] = s;
}

__global__ void reduce_wo(float* __restrict__ out)
{
    const int i = blockIdx.x * blockDim.x + threadIdx.x;
    const int b2 = i >> 10;
    const int nn = i & 1023;
    float4 s = make_float4(0.f, 0.f, 0.f, 0.f);
#pragma unroll
    for (int ky = 0; ky < SK_; ky++) {
        float4 v = reinterpret_cast<const float4*>(g_part)[(size_t)(ky * B_ + b2) * (QKV_N / 4) + nn];
        s.x += v.x; s.y += v.y; s.z += v.z; s.w += v.w;
    }
    reinterpret_cast<float4*>(out)[(size_t)b2 * 1024 + nn] = s;
}

// ---------------- flash-decode attention (FFMA2 + smem p-table) ------------
__global__ void __launch_bounds__(128)
attn_kernel(const float* __restrict__ kc, const float* __restrict__ vc)
{
    const int blk = blockIdx.x;
    const int sp  = blk & 3;
    const int g   = (blk >> 2) & 7;
    const int bb  = blk >> 5;
    const int tid = threadIdx.x;
    const int w   = tid >> 5;
    const int lane = tid & 31;

    __shared__ float q_s[NREP_][HD_];
    __shared__ float p_s[4][32][4];     // per-warp probability table
    for (int idx = tid; idx < NREP_ * HD_; idx += 128) {
        int h = idx >> 7, d = idx & 127;
        q_s[h][d] = g_qkv[bb * QKV_N + (g * NREP_ + h) * HD_ + d];
    }
    __syncthreads();

    const float scale = 0.08838834764831845f;   // 1/sqrt(128)
    float m[4], l[4];
    ull acc2[4][2];
#pragma unroll
    for (int h = 0; h < 4; h++) {
        m[h] = -1e30f; l[h] = 0.f;
        acc2[h][0] = 0ull; acc2[h][1] = 0ull;
    }

    const int tbase = sp * TOK_PER_SPLIT + w * TOK_PER_WARP;
    const float* knew = &g_qkv[bb * QKV_N + 4096 + g * HD_];
    const float* vnew = &g_qkv[bb * QKV_N + 5120 + g * HD_];

    for (int r = 0; r < 4; r++) {
        const int tb = tbase + r * 32;
        const int t  = tb + lane;
        const float* krow = (t == START_)
            ? knew
            : kc + (((size_t)bb * T_TOT + t) * NKV_ + g) * HD_;

        // ---- scores via FFMA2: 2 pair-accumulators per head ----
        ull s2[4][2];
#pragma unroll
        for (int h = 0; h < 4; h++) { s2[h][0] = 0ull; s2[h][1] = 0ull; }
#pragma unroll
        for (int i = 0; i < HD_ / 4; i++) {
            float4 k4 = __ldg(reinterpret_cast<const float4*>(krow) + i);
            ull ka = reinterpret_cast<const ull*>(&k4)[0];
            ull kb = reinterpret_cast<const ull*>(&k4)[1];
#pragma unroll
            for (int h = 0; h < 4; h++) {
                float4 q4 = *(reinterpret_cast<const float4*>(&q_s[h][0]) + i);
                ffma2(s2[h][0], ka, reinterpret_cast<const ull*>(&q4)[0]);
                ffma2(s2[h][1], kb, reinterpret_cast<const ull*>(&q4)[1]);
            }
        }
        // ---- online softmax ----
        float p[4];
#pragma unroll
        for (int h = 0; h < 4; h++) {
            float2 a = *reinterpret_cast<const float2*>(&s2[h][0]);
            float2 b = *reinterpret_cast<const float2*>(&s2[h][1]);
            float sc = (a.x + a.y + b.x + b.y) * scale;
            float mx = sc;
#pragma unroll
            for (int o = 16; o > 0; o >>= 1)
                mx = fmaxf(mx, __shfl_xor_sync(0xffffffffu, mx, o));
            float mnew = fmaxf(m[h], mx);
            float corr = __expf(m[h] - mnew);
            p[h] = __expf(sc - mnew);
            float ps = p[h];
#pragma unroll
            for (int o = 16; o > 0; o >>= 1)
                ps += __shfl_xor_sync(0xffffffffu, ps, o);
            l[h] = l[h] * corr + ps;
            m[h] = mnew;
            ull c2 = bcast2(corr);
            // rescale accumulators (pair multiply via ffma2 with zero add? use mul)
            asm("mul.rn.f32x2 %0, %0, %1;" : "+l"(acc2[h][0]) : "l"(c2));
            asm("mul.rn.f32x2 %0, %0, %1;" : "+l"(acc2[h][1]) : "l"(c2));
        }
        // publish p to warp-private smem table
        *reinterpret_cast<float4*>(&p_s[w][lane][0]) = make_float4(p[0], p[1], p[2], p[3]);
        __syncwarp();

        // ---- V accumulation: batched loads + broadcast p reads ----
#pragma unroll
        for (int tt0 = 0; tt0 < 32; tt0 += 8) {
            float4 v8[8];
#pragma unroll
            for (int u = 0; u < 8; u++) {
                const int t2 = tb + tt0 + u;
                const float* vrow = (t2 == START_)
                    ? vnew
                    : vc + (((size_t)bb * T_TOT + t2) * NKV_ + g) * HD_;
                v8[u] = __ldg(reinterpret_cast<const float4*>(vrow) + lane);
            }
#pragma unroll
            for (int u = 0; u < 8; u++) {
                float4 p4 = *reinterpret_cast<const float4*>(&p_s[w][tt0 + u][0]);
                ull va = reinterpret_cast<const ull*>(&v8[u])[0];
                ull vb = reinterpret_cast<const ull*>(&v8[u])[1];
                float pv[4] = {p4.x, p4.y, p4.z, p4.w};
#pragma unroll
                for (int h = 0; h < 4; h++) {
                    ull pt = bcast2(pv[h]);
                    ffma2(acc2[h][0], pt, va);
                    ffma2(acc2[h][1], pt, vb);
                }
            }
        }
        __syncwarp();
    }

    const int sp16 = sp * 4 + w;
#pragma unroll
    for (int h = 0; h < 4; h++) {
        const int hh = g * NREP_ + h;
        if (lane == 0) {
            g_pm[(bb * NH_ + hh) * NPART_ + sp16] = m[h];
            g_pl[(bb * NH_ + hh) * NPART_ + sp16] = l[h];
        }
        float2 lo = *reinterpret_cast<const float2*>(&acc2[h][0]);
        float2 hi = *reinterpret_cast<const float2*>(&acc2[h][1]);
        float4 o4 = make_float4(lo.x, lo.y, hi.x, hi.y);
        reinterpret_cast<float4*>(
            &g_po[(((size_t)bb * NH_ + hh) * NPART_ + sp16) * HD_])[lane] = o4;
    }
}

// ---------------- combine: 1 warp per (b,head), float4 lanes ----------------
__global__ void __launch_bounds__(128)
combine_kernel()
{
    const int w    = threadIdx.x >> 5;
    const int lane = threadIdx.x & 31;
    const int bh   = blockIdx.x * 4 + w;       // b*NH + h

    float mx = -1e30f;
#pragma unroll
    for (int s = 0; s < NPART_; s++)
        mx = fmaxf(mx, g_pm[bh * NPART_ + s]);
    float lsum = 0.f;
    float4 osum = make_float4(0.f, 0.f, 0.f, 0.f);
#pragma unroll
    for (int s = 0; s < NPART_; s++) {
        float wgt = __expf(g_pm[bh * NPART_ + s] - mx);
        lsum += g_pl[bh * NPART_ + s] * wgt;
        float4 o = reinterpret_cast<const float4*>(
            &g_po[((size_t)bh * NPART_ + s) * HD_])[lane];
        osum.x += wgt * o.x; osum.y += wgt * o.y;
        osum.z += wgt * o.z; osum.w += wgt * o.w;
    }
    float inv = 1.f / lsum;
    float4 r = make_float4(osum.x * inv, osum.y * inv, osum.z * inv, osum.w * inv);
    reinterpret_cast<float4*>(&g_attn[bh * HD_])[lane] = r;
}

// ---------------- launch ----------------------------------------------------
extern "C" void kernel_launch(void* const* d_in, const int* in_sizes, int n_in,
                              void* d_out, int out_size)
{
    (void)in_sizes; (void)n_in; (void)out_size;
    const float* x  = (const float*)d_in[0];
    const float* wq = (const float*)d_in[1];
    const float* wk = (const float*)d_in[2];
    const float* wv = (const float*)d_in[3];
    const float* wo = (const float*)d_in[4];
    const float* kc = (const float*)d_in[5];
    const float* vc = (const float*)d_in[6];
    const float* fc = (const float*)d_in[7];
    const float* fs = (const float*)d_in[8];
    float* out = (float*)d_out;

    gemm_qkv<<<dim3(48, SK_), 128>>>(x, wq, wk, wv);
    reduce_rope<<<(B_ * 3072) / 256, 256>>>(fc, fs);

    attn_kernel<<<B_ * NKV_ * SPLITS_, 128>>>(kc, vc);
    combine_kernel<<<B_ * NH_ / 4, 128>>>();

    gemm_o<<<dim3(32, SK_), 128>>>(wo);
    reduce_wo<<<(B_ * 1024) / 256, 256>>>(out);
}

// round 9
// speedup vs baseline: 1.1589x; 1.1589x over previous
#include <cuda_runtime.h>

#define B_      32
#define DIM_    4096
#define NH_     32
#define NKV_    8
#define HD_     128
#define NREP_   4
#define T_TOT   2048
#define START_  2047
#define QKV_N   6144
#define SK_     8
#define TILE_N  128
#define TILE_K  32
#define SPLITS_ 4
#define TOK_PER_SPLIT 512
#define TOK_PER_WARP  128
#define NPART_  16   // SPLITS_ * 4 warps
#define KT_ROWS 16          // K subtile rows per warp
#define KT_PITCH 132        // floats per row (528B -> conflict-free)

typedef unsigned long long ull;

// ---------------- scratch (device globals; no runtime allocation) ----------
__device__ float g_part[SK_ * B_ * QKV_N];
__device__ float g_qkv [B_ * QKV_N];
__device__ float g_attn[B_ * NH_ * HD_];
__device__ float g_pm  [B_ * NH_ * NPART_];
__device__ float g_pl  [B_ * NH_ * NPART_];
__device__ float g_po  [(size_t)B_ * NH_ * NPART_ * HD_];

// packed fp32x2 FMA (GEMM only; it measured a win there)
__device__ __forceinline__ void ffma2(ull& d, ull a, ull b)
{
    asm("fma.rn.f32x2 %0, %1, %2, %0;" : "+l"(d) : "l"(a), "l"(b));
}

// ---------------- split-K tall-skinny GEMM with K-pair FFMA2 ---------------
__device__ __forceinline__ void gemm_body(const float* __restrict__ A,
                                          const float* __restrict__ W,
                                          int N, int col0, int n0, int ky)
{
    __shared__ float xs[B_][TILE_K + 2];
    __shared__ float ws[TILE_N][TILE_K + 2];

    const int kbeg = ky * (DIM_ / SK_);
    const int tid  = threadIdx.x;
    const int tx   = tid & 15;
    const int ty   = tid >> 4;

    ull acc[4][8];
#pragma unroll
    for (int i = 0; i < 4; i++)
#pragma unroll
        for (int j = 0; j < 8; j++) acc[i][j] = 0ull;

    for (int kt = 0; kt < DIM_ / SK_; kt += TILE_K) {
        const int k0 = kbeg + kt;
#pragma unroll
        for (int it = 0; it < (TILE_K * TILE_N) / 128; it++) {
            int idx = tid + it * 128;
            int kk = idx >> 7;
            int nn = idx & 127;
            ws[nn][kk] = W[(size_t)(k0 + kk) * N + n0 + nn];
        }
#pragma unroll
        for (int it = 0; it < (B_ * TILE_K) / 128; it++) {
            int idx = tid + it * 128;
            int bb = idx >> 5;
            int kk = idx & 31;
            xs[bb][kk] = A[(size_t)bb * DIM_ + k0 + kk];
        }
        __syncthreads();
#pragma unroll
        for (int kp = 0; kp < TILE_K / 2; kp++) {
            ull xv[4], wv[8];
#pragma unroll
            for (int i = 0; i < 4; i++)
                xv[i] = *reinterpret_cast<const ull*>(&xs[ty + 8 * i][2 * kp]);
#pragma unroll
            for (int j = 0; j < 8; j++)
                wv[j] = *reinterpret_cast<const ull*>(&ws[tx + 16 * j][2 * kp]);
#pragma unroll
            for (int i = 0; i < 4; i++)
#pragma unroll
                for (int j = 0; j < 8; j++)
                    ffma2(acc[i][j], xv[i], wv[j]);
        }
        __syncthreads();
    }
#pragma unroll
    for (int i = 0; i < 4; i++) {
        int bb = ty + 8 * i;
#pragma unroll
        for (int j = 0; j < 8; j++) {
            float2 v = *reinterpret_cast<const float2*>(&acc[i][j]);
            int nn = col0 + n0 + tx + 16 * j;
            g_part[((size_t)ky * B_ + bb) * QKV_N + nn] = v.x + v.y;
        }
    }
}

__global__ void __launch_bounds__(128)
gemm_qkv(const float* __restrict__ x, const float* __restrict__ wq,
         const float* __restrict__ wk, const float* __restrict__ wv)
{
    const int tile = blockIdx.x;
    const int ky   = blockIdx.y;
    if (tile < 32)       gemm_body(x, wq, 4096, 0,    tile * TILE_N,        ky);
    else if (tile < 40)  gemm_body(x, wk, 1024, 4096, (tile - 32) * TILE_N, ky);
    else                 gemm_body(x, wv, 1024, 5120, (tile - 40) * TILE_N, ky);
}

__global__ void __launch_bounds__(128)
gemm_o(const float* __restrict__ W)
{
    gemm_body(g_attn, W, 4096, 0, blockIdx.x * TILE_N, blockIdx.y);
}

// ---------------- fused reduce + RoPE (float2 pairs) -----------------------
__global__ void reduce_rope(const float* __restrict__ fc, const float* __restrict__ fs)
{
    const int idx = blockIdx.x * blockDim.x + threadIdx.x;
    const int b2  = idx / 3072;
    const int cp  = idx - b2 * 3072;
    float2 s = make_float2(0.f, 0.f);
#pragma unroll
    for (int ky = 0; ky < SK_; ky++) {
        float2 v = reinterpret_cast<const float2*>(g_part)[(size_t)(ky * B_ + b2) * 3072 + cp];
        s.x += v.x; s.y += v.y;
    }
    if (cp < 2560) {
        int f = cp & 63;
        float c = fc[f], sn = fs[f];
        float xr = s.x, xi = s.y;
        s.x = xr * c - xi * sn;
        s.y = xr * sn + xi * c;
    }
    reinterpret_cast<float2*>(g_qkv)[(size_t)b2 * 3072 + cp] = s;
}

__global__ void reduce_wo(float* __restrict__ out)
{
    const int i = blockIdx.x * blockDim.x + threadIdx.x;
    const int b2 = i >> 10;
    const int nn = i & 1023;
    float4 s = make_float4(0.f, 0.f, 0.f, 0.f);
#pragma unroll
    for (int ky = 0; ky < SK_; ky++) {
        float4 v = reinterpret_cast<const float4*>(g_part)[(size_t)(ky * B_ + b2) * (QKV_N / 4) + nn];
        s.x += v.x; s.y += v.y; s.z += v.z; s.w += v.w;
    }
    reinterpret_cast<float4*>(out)[(size_t)b2 * 1024 + nn] = s;
}

// ---------------- flash-decode attention (coalesced K via SMEM) ------------
// grid: b(32)*g(8)*split(4), 128 threads. 16-token subtiles per warp.
__global__ void __launch_bounds__(128)
attn_kernel(const float* __restrict__ kc, const float* __restrict__ vc)
{
    const int blk = blockIdx.x;
    const int sp  = blk & 3;
    const int g   = (blk >> 2) & 7;
    const int bb  = blk >> 5;
    const int tid = threadIdx.x;
    const int w   = tid >> 5;
    const int lane = tid & 31;

    __shared__ float q_s[NREP_][HD_];
    __shared__ float ktile[4][KT_ROWS][KT_PITCH];   // per-warp K subtile, padded pitch

    for (int idx = tid; idx < NREP_ * HD_; idx += 128) {
        int h = idx >> 7, d = idx & 127;
        q_s[h][d] = g_qkv[bb * QKV_N + (g * NREP_ + h) * HD_ + d];
    }
    __syncthreads();

    const float scale = 0.08838834764831845f;   // 1/sqrt(128)
    float m[4], l[4], acc[4][4];
#pragma unroll
    for (int h = 0; h < 4; h++) {
        m[h] = -1e30f; l[h] = 0.f;
#pragma unroll
        for (int j = 0; j < 4; j++) acc[h][j] = 0.f;
    }

    const int tbase = sp * TOK_PER_SPLIT + w * TOK_PER_WARP;
    const float* knew = &g_qkv[bb * QKV_N + 4096 + g * HD_];
    const float* vnew = &g_qkv[bb * QKV_N + 5120 + g * HD_];

    const int tkn  = lane & 15;     // token within subtile
    const int half = lane >> 4;     // dim half (0: dims 0-63, 1: 64-127)

    for (int r = 0; r < TOK_PER_WARP / KT_ROWS; r++) {       // 8 subtiles of 16
        const int tb = tbase + r * KT_ROWS;

        // ---- coalesced K fill: warp loads one 512B row per iteration ----
#pragma unroll
        for (int rr = 0; rr < KT_ROWS; rr++) {
            const int t = tb + rr;
            const float* krow = (t == START_)
                ? knew
                : kc + (((size_t)bb * T_TOT + t) * NKV_ + g) * HD_;
            float4 kv = __ldg(reinterpret_cast<const float4*>(krow) + lane);
            *reinterpret_cast<float4*>(&ktile[w][rr][lane * 4]) = kv;
        }
        __syncwarp();

        // ---- scores from SMEM: 2 lanes per token, 64 dims each ----
        float s4[4] = {0.f, 0.f, 0.f, 0.f};
#pragma unroll
        for (int i = 0; i < 16; i++) {
            float4 k4 = *reinterpret_cast<const float4*>(&ktile[w][tkn][half * 64 + i * 4]);
#pragma unroll
            for (int h = 0; h < 4; h++) {
                float4 q4 = *(reinterpret_cast<const float4*>(&q_s[h][half * 64]) + i);
                s4[h] += k4.x * q4.x + k4.y * q4.y + k4.z * q4.z + k4.w * q4.w;
            }
        }
        __syncwarp();

        float p[4];
#pragma unroll
        for (int h = 0; h < 4; h++) {
            float sc = (s4[h] + __shfl_xor_sync(0xffffffffu, s4[h], 16)) * scale;
            // 16 distinct tokens, duplicated across halves -> 4-level trees
            float mx = sc;
#pragma unroll
            for (int o = 8; o > 0; o >>= 1)
                mx = fmaxf(mx, __shfl_xor_sync(0xffffffffu, mx, o));
            float mnew = fmaxf(m[h], mx);
            float corr = __expf(m[h] - mnew);
            p[h] = __expf(sc - mnew);
            float ps = p[h];
#pragma unroll
            for (int o = 8; o > 0; o >>= 1)
                ps += __shfl_xor_sync(0xffffffffu, ps, o);
            l[h] = l[h] * corr + ps;
            m[h] = mnew;
#pragma unroll
            for (int j = 0; j < 4; j++) acc[h][j] *= corr;
        }

        // ---- V accumulation (coalesced, batched 8 for MLP) ----
#pragma unroll
        for (int tt0 = 0; tt0 < KT_ROWS; tt0 += 8) {
            float4 v8[8];
#pragma unroll
            for (int u = 0; u < 8; u++) {
                const int t2 = tb + tt0 + u;
                const float* vrow = (t2 == START_)
                    ? vnew
                    : vc + (((size_t)bb * T_TOT + t2) * NKV_ + g) * HD_;
                v8[u] = __ldg(reinterpret_cast<const float4*>(vrow) + lane);
            }
#pragma unroll
            for (int u = 0; u < 8; u++) {
                float pt[4];
#pragma unroll
                for (int h = 0; h < 4; h++)
                    pt[h] = __shfl_sync(0xffffffffu, p[h], tt0 + u);
#pragma unroll
                for (int h = 0; h < 4; h++) {
                    acc[h][0] += pt[h] * v8[u].x;
                    acc[h][1] += pt[h] * v8[u].y;
                    acc[h][2] += pt[h] * v8[u].z;
                    acc[h][3] += pt[h] * v8[u].w;
                }
            }
        }
    }

    const int sp16 = sp * 4 + w;
#pragma unroll
    for (int h = 0; h < 4; h++) {
        const int hh = g * NREP_ + h;
        if (lane == 0) {
            g_pm[(bb * NH_ + hh) * NPART_ + sp16] = m[h];
            g_pl[(bb * NH_ + hh) * NPART_ + sp16] = l[h];
        }
        float4 o4 = make_float4(acc[h][0], acc[h][1], acc[h][2], acc[h][3]);
        reinterpret_cast<float4*>(
            &g_po[(((size_t)bb * NH_ + hh) * NPART_ + sp16) * HD_])[lane] = o4;
    }
}

// ---------------- combine 16 partials per (b, head) ------------------------
__global__ void combine_kernel()
{
    const int bh = blockIdx.x;       // b*NH + h
    const int d  = threadIdx.x;      // 128
    float mx = -1e30f;
#pragma unroll
    for (int s = 0; s < NPART_; s++)
        mx = fmaxf(mx, g_pm[bh * NPART_ + s]);
    float lsum = 0.f, osum = 0.f;
#pragma unroll
    for (int s = 0; s < NPART_; s++) {
        float wgt = __expf(g_pm[bh * NPART_ + s] - mx);
        lsum += g_pl[bh * NPART_ + s] * wgt;
        osum += wgt * g_po[((size_t)bh * NPART_ + s) * HD_ + d];
    }
    g_attn[bh * HD_ + d] = osum / lsum;
}

// ---------------- launch ----------------------------------------------------
extern "C" void kernel_launch(void* const* d_in, const int* in_sizes, int n_in,
                              void* d_out, int out_size)
{
    (void)in_sizes; (void)n_in; (void)out_size;
    const float* x  = (const float*)d_in[0];
    const float* wq = (const float*)d_in[1];
    const float* wk = (const float*)d_in[2];
    const float* wv = (const float*)d_in[3];
    const float* wo = (const float*)d_in[4];
    const float* kc = (const float*)d_in[5];
    const float* vc = (const float*)d_in[6];
    const float* fc = (const float*)d_in[7];
    const float* fs = (const float*)d_in[8];
    float* out = (float*)d_out;

    gemm_qkv<<<dim3(48, SK_), 128>>>(x, wq, wk, wv);
    reduce_rope<<<(B_ * 3072) / 256, 256>>>(fc, fs);

    attn_kernel<<<B_ * NKV_ * SPLITS_, 128>>>(kc, vc);
    combine_kernel<<<B_ * NH_, 128>>>();

    gemm_o<<<dim3(32, SK_), 128>>>(wo);
    reduce_wo<<<(B_ * 1024) / 256, 256>>>(out);
}

// round 10
// speedup vs baseline: 1.2613x; 1.0884x over previous
#include <cuda_runtime.h>

#define B_      32
#define DIM_    4096
#define NH_     32
#define NKV_    8
#define HD_     128
#define NREP_   4
#define T_TOT   2048
#define START_  2047
#define QKV_N   6144
#define SK_     8
#define TILE_N  128
#define TILE_K  32
#define SPLITS_ 4
#define TOK_PER_SPLIT 512
#define TOK_PER_WARP  128
#define NPART_  16   // SPLITS_ * 4 warps
#define KT_ROWS 8           // K subtile rows per warp (8 -> 19KB smem -> 12 CTA/SM, single wave)
#define KT_PITCH 132        // floats per row (528B -> conflict-free)

typedef unsigned long long ull;

// ---------------- scratch (device globals; no runtime allocation) ----------
__device__ float g_part[SK_ * B_ * QKV_N];
__device__ float g_qkv [B_ * QKV_N];
__device__ float g_attn[B_ * NH_ * HD_];
__device__ float g_pm  [B_ * NH_ * NPART_];
__device__ float g_pl  [B_ * NH_ * NPART_];
__device__ float g_po  [(size_t)B_ * NH_ * NPART_ * HD_];

// packed fp32x2 FMA (GEMM only; measured win there)
__device__ __forceinline__ void ffma2(ull& d, ull a, ull b)
{
    asm("fma.rn.f32x2 %0, %1, %2, %0;" : "+l"(d) : "l"(a), "l"(b));
}

// ---------------- split-K tall-skinny GEMM with K-pair FFMA2 ---------------
__device__ __forceinline__ void gemm_body(const float* __restrict__ A,
                                          const float* __restrict__ W,
                                          int N, int col0, int n0, int ky)
{
    __shared__ float xs[B_][TILE_K + 2];
    __shared__ float ws[TILE_N][TILE_K + 2];

    const int kbeg = ky * (DIM_ / SK_);
    const int tid  = threadIdx.x;
    const int tx   = tid & 15;
    const int ty   = tid >> 4;

    ull acc[4][8];
#pragma unroll
    for (int i = 0; i < 4; i++)
#pragma unroll
        for (int j = 0; j < 8; j++) acc[i][j] = 0ull;

    for (int kt = 0; kt < DIM_ / SK_; kt += TILE_K) {
        const int k0 = kbeg + kt;
#pragma unroll
        for (int it = 0; it < (TILE_K * TILE_N) / 128; it++) {
            int idx = tid + it * 128;
            int kk = idx >> 7;
            int nn = idx & 127;
            ws[nn][kk] = W[(size_t)(k0 + kk) * N + n0 + nn];
        }
#pragma unroll
        for (int it = 0; it < (B_ * TILE_K) / 128; it++) {
            int idx = tid + it * 128;
            int bb = idx >> 5;
            int kk = idx & 31;
            xs[bb][kk] = A[(size_t)bb * DIM_ + k0 + kk];
        }
        __syncthreads();
#pragma unroll
        for (int kp = 0; kp < TILE_K / 2; kp++) {
            ull xv[4], wv[8];
#pragma unroll
            for (int i = 0; i < 4; i++)
                xv[i] = *reinterpret_cast<const ull*>(&xs[ty + 8 * i][2 * kp]);
#pragma unroll
            for (int j = 0; j < 8; j++)
                wv[j] = *reinterpret_cast<const ull*>(&ws[tx + 16 * j][2 * kp]);
#pragma unroll
            for (int i = 0; i < 4; i++)
#pragma unroll
                for (int j = 0; j < 8; j++)
                    ffma2(acc[i][j], xv[i], wv[j]);
        }
        __syncthreads();
    }
#pragma unroll
    for (int i = 0; i < 4; i++) {
        int bb = ty + 8 * i;
#pragma unroll
        for (int j = 0; j < 8; j++) {
            float2 v = *reinterpret_cast<const float2*>(&acc[i][j]);
            int nn = col0 + n0 + tx + 16 * j;
            g_part[((size_t)ky * B_ + bb) * QKV_N + nn] = v.x + v.y;
        }
    }
}

__global__ void __launch_bounds__(128)
gemm_qkv(const float* __restrict__ x, const float* __restrict__ wq,
         const float* __restrict__ wk, const float* __restrict__ wv)
{
    const int tile = blockIdx.x;
    const int ky   = blockIdx.y;
    if (tile < 32)       gemm_body(x, wq, 4096, 0,    tile * TILE_N,        ky);
    else if (tile < 40)  gemm_body(x, wk, 1024, 4096, (tile - 32) * TILE_N, ky);
    else                 gemm_body(x, wv, 1024, 5120, (tile - 40) * TILE_N, ky);
}

__global__ void __launch_bounds__(128)
gemm_o(const float* __restrict__ W)
{
    gemm_body(g_attn, W, 4096, 0, blockIdx.x * TILE_N, blockIdx.y);
}

// ---------------- fused reduce + RoPE (float2 pairs) -----------------------
__global__ void reduce_rope(const float* __restrict__ fc, const float* __restrict__ fs)
{
    const int idx = blockIdx.x * blockDim.x + threadIdx.x;
    const int b2  = idx / 3072;
    const int cp  = idx - b2 * 3072;
    float2 s = make_float2(0.f, 0.f);
#pragma unroll
    for (int ky = 0; ky < SK_; ky++) {
        float2 v = reinterpret_cast<const float2*>(g_part)[(size_t)(ky * B_ + b2) * 3072 + cp];
        s.x += v.x; s.y += v.y;
    }
    if (cp < 2560) {
        int f = cp & 63;
        float c = fc[f], sn = fs[f];
        float xr = s.x, xi = s.y;
        s.x = xr * c - xi * sn;
        s.y = xr * sn + xi * c;
    }
    reinterpret_cast<float2*>(g_qkv)[(size_t)b2 * 3072 + cp] = s;
}

__global__ void reduce_wo(float* __restrict__ out)
{
    const int i = blockIdx.x * blockDim.x + threadIdx.x;
    const int b2 = i >> 10;
    const int nn = i & 1023;
    float4 s = make_float4(0.f, 0.f, 0.f, 0.f);
#pragma unroll
    for (int ky = 0; ky < SK_; ky++) {
        float4 v = reinterpret_cast<const float4*>(g_part)[(size_t)(ky * B_ + b2) * (QKV_N / 4) + nn];
        s.x += v.x; s.y += v.y; s.z += v.z; s.w += v.w;
    }
    reinterpret_cast<float4*>(out)[(size_t)b2 * 1024 + nn] = s;
}

// ---------------- flash-decode attention (single-wave, 8-token subtiles) ---
// grid: b(32)*g(8)*split(4), 128 threads. ~19KB smem -> 12 CTAs/SM -> 1 wave.
__global__ void __launch_bounds__(128)
attn_kernel(const float* __restrict__ kc, const float* __restrict__ vc)
{
    const int blk = blockIdx.x;
    const int sp  = blk & 3;
    const int g   = (blk >> 2) & 7;
    const int bb  = blk >> 5;
    const int tid = threadIdx.x;
    const int w   = tid >> 5;
    const int lane = tid & 31;

    __shared__ float q_s[NREP_][HD_];
    __shared__ float ktile[4][KT_ROWS][KT_PITCH];   // per-warp K subtile

    for (int idx = tid; idx < NREP_ * HD_; idx += 128) {
        int h = idx >> 7, d = idx & 127;
        q_s[h][d] = g_qkv[bb * QKV_N + (g * NREP_ + h) * HD_ + d];
    }
    __syncthreads();

    const float scale = 0.08838834764831845f;   // 1/sqrt(128)
    float m[4], l[4], acc[4][4];
#pragma unroll
    for (int h = 0; h < 4; h++) {
        m[h] = -1e30f; l[h] = 0.f;
#pragma unroll
        for (int j = 0; j < 4; j++) acc[h][j] = 0.f;
    }

    const int tbase = sp * TOK_PER_SPLIT + w * TOK_PER_WARP;
    const float* knew = &g_qkv[bb * QKV_N + 4096 + g * HD_];
    const float* vnew = &g_qkv[bb * QKV_N + 5120 + g * HD_];

    const int tkn = lane & 7;      // token within 8-row subtile
    const int q4i = lane >> 3;     // dim quarter (32 dims each)

    for (int r = 0; r < TOK_PER_WARP / KT_ROWS; r++) {       // 16 subtiles of 8
        const int tb = tbase + r * KT_ROWS;

        // ---- coalesced K fill: one 512B row per iteration ----
#pragma unroll
        for (int rr = 0; rr < KT_ROWS; rr++) {
            const int t = tb + rr;
            const float* krow = (t == START_)
                ? knew
                : kc + (((size_t)bb * T_TOT + t) * NKV_ + g) * HD_;
            float4 kv = __ldg(reinterpret_cast<const float4*>(krow) + lane);
            *reinterpret_cast<float4*>(&ktile[w][rr][lane * 4]) = kv;
        }
        __syncwarp();

        // ---- scores: 4 lanes per token, 32 dims each ----
        float s4[4] = {0.f, 0.f, 0.f, 0.f};
#pragma unroll
        for (int i = 0; i < 8; i++) {
            float4 k4 = *reinterpret_cast<const float4*>(&ktile[w][tkn][q4i * 32 + i * 4]);
#pragma unroll
            for (int h = 0; h < 4; h++) {
                float4 q4 = *(reinterpret_cast<const float4*>(&q_s[h][q4i * 32]) + i);
                s4[h] += k4.x * q4.x + k4.y * q4.y + k4.z * q4.z + k4.w * q4.w;
            }
        }
        __syncwarp();

        float p[4];
#pragma unroll
        for (int h = 0; h < 4; h++) {
            // merge dim quarters (lane bits 3,4), then trees over 8 tokens (bits 0..2)
            float sc = s4[h];
            sc += __shfl_xor_sync(0xffffffffu, sc, 8);
            sc += __shfl_xor_sync(0xffffffffu, sc, 16);
            sc *= scale;
            float mx = sc;
#pragma unroll
            for (int o = 4; o > 0; o >>= 1)
                mx = fmaxf(mx, __shfl_xor_sync(0xffffffffu, mx, o));
            float mnew = fmaxf(m[h], mx);
            float corr = __expf(m[h] - mnew);
            p[h] = __expf(sc - mnew);
            float ps = p[h];
#pragma unroll
            for (int o = 4; o > 0; o >>= 1)
                ps += __shfl_xor_sync(0xffffffffu, ps, o);
            l[h] = l[h] * corr + ps;
            m[h] = mnew;
#pragma unroll
            for (int j = 0; j < 4; j++) acc[h][j] *= corr;
        }

        // ---- V accumulation (coalesced, batched 8 for MLP) ----
        {
            float4 v8[KT_ROWS];
#pragma unroll
            for (int u = 0; u < KT_ROWS; u++) {
                const int t2 = tb + u;
                const float* vrow = (t2 == START_)
                    ? vnew
                    : vc + (((size_t)bb * T_TOT + t2) * NKV_ + g) * HD_;
                v8[u] = __ldg(reinterpret_cast<const float4*>(vrow) + lane);
            }
#pragma unroll
            for (int u = 0; u < KT_ROWS; u++) {
                float pt[4];
#pragma unroll
                for (int h = 0; h < 4; h++)
                    pt[h] = __shfl_sync(0xffffffffu, p[h], u);
#pragma unroll
                for (int h = 0; h < 4; h++) {
                    acc[h][0] += pt[h] * v8[u].x;
                    acc[h][1] += pt[h] * v8[u].y;
                    acc[h][2] += pt[h] * v8[u].z;
                    acc[h][3] += pt[h] * v8[u].w;
                }
            }
        }
    }

    const int sp16 = sp * 4 + w;
#pragma unroll
    for (int h = 0; h < 4; h++) {
        const int hh = g * NREP_ + h;
        if (lane == 0) {
            g_pm[(bb * NH_ + hh) * NPART_ + sp16] = m[h];
            g_pl[(bb * NH_ + hh) * NPART_ + sp16] = l[h];
        }
        float4 o4 = make_float4(acc[h][0], acc[h][1], acc[h][2], acc[h][3]);
        reinterpret_cast<float4*>(
            &g_po[(((size_t)bb * NH_ + hh) * NPART_ + sp16) * HD_])[lane] = o4;
    }
}

// ---------------- combine 16 partials per (b, head) ------------------------
__global__ void combine_kernel()
{
    const int bh = blockIdx.x;       // b*NH + h
    const int d  = threadIdx.x;      // 128
    float mx = -1e30f;
#pragma unroll
    for (int s = 0; s < NPART_; s++)
        mx = fmaxf(mx, g_pm[bh * NPART_ + s]);
    float lsum = 0.f, osum = 0.f;
#pragma unroll
    for (int s = 0; s < NPART_; s++) {
        float wgt = __expf(g_pm[bh * NPART_ + s] - mx);
        lsum += g_pl[bh * NPART_ + s] * wgt;
        osum += wgt * g_po[((size_t)bh * NPART_ + s) * HD_ + d];
    }
    g_attn[bh * HD_ + d] = osum / lsum;
}

// ---------------- launch ----------------------------------------------------
extern "C" void kernel_launch(void* const* d_in, const int* in_sizes, int n_in,
                              void* d_out, int out_size)
{
    (void)in_sizes; (void)n_in; (void)out_size;
    const float* x  = (const float*)d_in[0];
    const float* wq = (const float*)d_in[1];
    const float* wk = (const float*)d_in[2];
    const float* wv = (const float*)d_in[3];
    const float* wo = (const float*)d_in[4];
    const float* kc = (const float*)d_in[5];
    const float* vc = (const float*)d_in[6];
    const float* fc = (const float*)d_in[7];
    const float* fs = (const float*)d_in[8];
    float* out = (float*)d_out;

    gemm_qkv<<<dim3(48, SK_), 128>>>(x, wq, wk, wv);
    reduce_rope<<<(B_ * 3072) / 256, 256>>>(fc, fs);

    attn_kernel<<<B_ * NKV_ * SPLITS_, 128>>>(kc, vc);
    combine_kernel<<<B_ * NH_, 128>>>();

    gemm_o<<<dim3(32, SK_), 128>>>(wo);
    reduce_wo<<<(B_ * 1024) / 256, 256>>>(out);
}